// round 8
// baseline (speedup 1.0000x reference)
#include <cuda_runtime.h>
#include <cuda_bf16.h>

#define N_COLS   4096
#define N_TERMS  2048
#define COL4     1024              // float4 columns
#define ROW_BLOCKS 128
#define ROWS_PER   16
#define K2_BLOCKS  16              // stats slices: 16 x 256 threads = 4096 columns
#define TOTAL_BLK  1536            // KA grid: 512 reduce tiles + 1024 zero tiles

// ---- scratch (device globals; no allocation allowed) ----
__device__ float    g_partial[ROW_BLOCKS * N_COLS];   // 2 MB partial |x| column sums
__device__ float4   g_scale4[COL4];                   // per-column generator scale
__device__ float4   g_val4[COL4];                     // per-column delta*0.5*crossf
__device__ int4     g_cross4[COL4];                   // per-column crossing flag
__device__ int4     g_rank4[COL4];                    // per-column local rank in 256-col slice
__device__ int      g_bcount[K2_BLOCKS];              // crossings per 256-col slice
__device__ unsigned g_done;                           // KA completion tickets (reset each launch)
__device__ unsigned g_done2;                          // stats-slice completion (reset each launch)

// KA: interleaved reduce (|x| partial col sums) + tail-zero tiles, then the
// last 16 finishing blocks compute per-column stats + block-local scan.
__global__ __launch_bounds__(256) void kA(const float* __restrict__ x,
                                          float* __restrict__ out) {
    int t   = threadIdx.x;                 // 0..255
    int bid = blockIdx.x;                  // 0..1535
    const float4* x4 = (const float4*)x;
    float4*       o4 = (float4*)out;

    if (bid % 3 == 0) {
        // reduce tile 0..511: 16 rows x 256 col4
        int tile = bid / 3;
        int col4 = (tile & 3) * 256 + t;
        int cy   = tile >> 2;              // 0..127
        int r0   = 1 + cy * ROWS_PER;
        float4 acc = make_float4(0.f, 0.f, 0.f, 0.f);
        #pragma unroll
        for (int r = 0; r < ROWS_PER; r++) {
            int row = r0 + r;
            if (row < N_TERMS) {
                float4 v = x4[(size_t)row * COL4 + col4];
                acc.x += fabsf(v.x);
                acc.y += fabsf(v.y);
                acc.z += fabsf(v.z);
                acc.w += fabsf(v.w);
            }
        }
        ((float4*)&g_partial[cy * N_COLS])[col4] = acc;
    } else {
        // zero tile 0..1023: rows 2048..6143
        int tile = bid - bid / 3 - 1;
        int col4 = (tile & 3) * 256 + t;
        int r0   = N_TERMS + (tile >> 2) * ROWS_PER;
        const float4 z = make_float4(0.f, 0.f, 0.f, 0.f);
        #pragma unroll
        for (int r = 0; r < ROWS_PER; r++)
            o4[(size_t)(r0 + r) * COL4 + col4] = z;
    }

    // ---- completion ticket; last 16 blocks run the stats phase ----
    __threadfence();
    __syncthreads();
    __shared__ unsigned s_ticket;
    if (t == 0) s_ticket = atomicAdd(&g_done, 1u);
    __syncthreads();
    unsigned ticket = s_ticket;
    if (ticket < TOTAL_BLK - K2_BLOCKS) return;

    if (t == 0) {                          // wait until every block has arrived
        volatile unsigned* p = &g_done;
        while (*p < TOTAL_BLK) { }
    }
    __syncthreads();
    __threadfence();                       // acquire: g_partial writes now visible

    // ---- stats + local scan for 256-column slice b ----
    {
        __shared__ int s_wsum[8];
        int b    = (int)(ticket - (TOTAL_BLK - K2_BLOCKS));  // 0..15
        int col  = b * 256 + t;
        int lane = t & 31, wid = t >> 5;

        float s = 0.f;
        #pragma unroll 16
        for (int rb = 0; rb < ROW_BLOCKS; rb++)
            s += g_partial[rb * N_COLS + col];

        float c     = x[col];              // x[0] center row
        float upper = c + s;
        float lower = c - s;
        bool  cross = (lower * upper) < 0.f;
        bool  pos   = lower >= 0.f;
        float crossf = cross ? 1.f : 0.f;
        float posf   = pos   ? 1.f : 0.f;

        float denom = upper - lower;
        float ratio = (denom != 0.f) ? (upper / denom) : 0.5f;
        float lam   = posf + crossf * ratio;

        float delta  = fmaxf(-lam * lower, (1.f - lam) * upper);
        float center = (delta * 0.5f + lam * c) * crossf + c * posf;

        ((float*)g_scale4)[col] = lam * crossf + posf;
        ((float*)g_val4)[col]   = delta * 0.5f * crossf;
        ((int*)g_cross4)[col]   = cross ? 1 : 0;
        out[col] = center;

        int flag = cross ? 1 : 0;
        int v = flag;
        #pragma unroll
        for (int o = 1; o < 32; o <<= 1) {
            int n = __shfl_up_sync(0xffffffffu, v, o);
            if (lane >= o) v += n;
        }
        if (lane == 31) s_wsum[wid] = v;
        __syncthreads();
        if (t < 8) {
            int wv = s_wsum[t];
            #pragma unroll
            for (int o = 1; o < 8; o <<= 1) {
                int n = __shfl_up_sync(0x000000ffu, wv, o);
                if (t >= o) wv += n;
            }
            s_wsum[t] = wv;
            if (t == 7) g_bcount[b] = wv;
        }
        __syncthreads();

        int rank = (v - flag) + ((wid > 0) ? s_wsum[wid - 1] : 0);
        ((int*)g_rank4)[col] = rank;
    }

    // ---- deterministic counter reset for the next graph replay ----
    __threadfence();
    __syncthreads();
    if (t == 0) {
        unsigned d = atomicAdd(&g_done2, 1u);
        if (d == K2_BLOCKS - 1) {
            atomicExch(&g_done, 0u);
            atomicExch(&g_done2, 0u);
        }
    }
}

// KB: y<128 -> gens rows 1..2047; y==128 -> scatter into the pre-zeroed tail.
__global__ __launch_bounds__(256) void kB(const float* __restrict__ x,
                                          float* __restrict__ out) {
    int cy = blockIdx.y;
    if (cy < ROW_BLOCKS) {
        int col4 = blockIdx.x * blockDim.x + threadIdx.x;   // 0..1023
        const float4* x4 = (const float4*)x;
        float4* o4 = (float4*)out;
        float4 sc = g_scale4[col4];
        int r0 = 1 + cy * ROWS_PER;
        #pragma unroll
        for (int r = 0; r < ROWS_PER; r++) {
            int row = r0 + r;
            if (row < N_TERMS) {
                float4 v = x4[(size_t)row * COL4 + col4];
                v.x *= sc.x; v.y *= sc.y; v.z *= sc.z; v.w *= sc.w;
                o4[(size_t)row * COL4 + col4] = v;
            }
        }
    } else {
        // 4 x-blocks * 256 threads = 1024 threads, 4 consecutive columns each
        int i = blockIdx.x * blockDim.x + threadIdx.x;      // 0..1023
        int4   cf  = g_cross4[i];
        int4   rk  = g_rank4[i];
        float4 val = g_val4[i];
        int blk = i >> 6;                                   // (4*i)/256
        int base = 0;
        #pragma unroll
        for (int k = 0; k < K2_BLOCKS; k++)
            base += (k < blk) ? g_bcount[k] : 0;

        int col = i * 4;
        if (cf.x) out[(size_t)(N_TERMS + base + rk.x) * N_COLS + col + 0] = val.x;
        if (cf.y) out[(size_t)(N_TERMS + base + rk.y) * N_COLS + col + 1] = val.y;
        if (cf.z) out[(size_t)(N_TERMS + base + rk.z) * N_COLS + col + 2] = val.z;
        if (cf.w) out[(size_t)(N_TERMS + base + rk.w) * N_COLS + col + 3] = val.w;
    }
}

extern "C" void kernel_launch(void* const* d_in, const int* in_sizes, int n_in,
                              void* d_out, int out_size) {
    const float* x = (const float*)d_in[0];
    float* out     = (float*)d_out;

    kA<<<TOTAL_BLK, 256>>>(x, out);
    dim3 gb(COL4 / 256, ROW_BLOCKS + 1);                 // (4, 129)
    kB<<<gb, 256>>>(x, out);
}

// round 9
// speedup vs baseline: 1.0888x; 1.0888x over previous
#include <cuda_runtime.h>
#include <cuda_bf16.h>

#define N_COLS   4096
#define N_TERMS  2048
#define COL4     1024              // float4 columns
#define ROW_BLOCKS 128
#define ROWS_PER   16
#define K2_BLOCKS  16              // 16 blocks x 256 threads = 4096 columns
#define K1_BLOCKS  1536            // 512 reduce tiles + 1024 zero tiles

// ---- scratch (device globals; no allocation allowed) ----
__device__ float  g_partial[ROW_BLOCKS * N_COLS];   // 2 MB partial |x| column sums
__device__ float4 g_scale4[COL4];                   // per-column generator scale
__device__ float4 g_val4[COL4];                     // per-column delta*0.5*crossf
__device__ int4   g_cross4[COL4];                   // per-column crossing flag
__device__ int4   g_rank4[COL4];                    // per-column local rank in 256-col slice
__device__ int    g_bcount[K2_BLOCKS];              // crossings per 256-col slice

// K1: flat grid, read/write tiles interleaved 1:2 so every wave carries both
// the |x| reduction reads and the tail-zero writes.
__global__ __launch_bounds__(256) void k1_reduce_zero(const float* __restrict__ x,
                                                      float* __restrict__ out) {
    int t   = threadIdx.x;                 // 0..255
    int bid = blockIdx.x;                  // 0..1535

    if (bid % 3 == 0) {
        // reduce tile 0..511: 16 rows x 256 col4
        int tile = bid / 3;
        int col4 = (tile & 3) * 256 + t;
        int cy   = tile >> 2;              // 0..127
        int r0   = 1 + cy * ROWS_PER;
        const float4* x4 = (const float4*)x;
        float4 acc = make_float4(0.f, 0.f, 0.f, 0.f);
        #pragma unroll
        for (int r = 0; r < ROWS_PER; r++) {
            int row = r0 + r;
            if (row < N_TERMS) {
                float4 v = x4[(size_t)row * COL4 + col4];
                acc.x += fabsf(v.x);
                acc.y += fabsf(v.y);
                acc.z += fabsf(v.z);
                acc.w += fabsf(v.w);
            }
        }
        ((float4*)&g_partial[cy * N_COLS])[col4] = acc;
    } else {
        // zero tile 0..1023: rows 2048..6143
        int tile = bid - bid / 3 - 1;
        int col4 = (tile & 3) * 256 + t;
        int r0   = N_TERMS + (tile >> 2) * ROWS_PER;
        float4* o4 = (float4*)out;
        const float4 z = make_float4(0.f, 0.f, 0.f, 0.f);
        #pragma unroll
        for (int r = 0; r < ROWS_PER; r++)
            o4[(size_t)(r0 + r) * COL4 + col4] = z;
    }
}

// K2: per-column stats + center row + block-local scan of crossing flags.
__global__ __launch_bounds__(256) void k2_stats(const float* __restrict__ x,
                                                float* __restrict__ out) {
    __shared__ int s_wsum[8];
    int t   = threadIdx.x;                  // 0..255
    int b   = blockIdx.x;                   // 0..15
    int col = b * 256 + t;
    int lane = t & 31, wid = t >> 5;        // 8 warps

    float s = 0.f;
    #pragma unroll 16
    for (int rb = 0; rb < ROW_BLOCKS; rb++)
        s += g_partial[rb * N_COLS + col];

    float c     = x[col];                   // x[0] center row
    float upper = c + s;
    float lower = c - s;
    bool  cross = (lower * upper) < 0.f;
    bool  pos   = lower >= 0.f;
    float crossf = cross ? 1.f : 0.f;
    float posf   = pos   ? 1.f : 0.f;

    float denom = upper - lower;
    float ratio = (denom != 0.f) ? (upper / denom) : 0.5f;
    float lam   = posf + crossf * ratio;

    float delta  = fmaxf(-lam * lower, (1.f - lam) * upper);
    float center = (delta * 0.5f + lam * c) * crossf + c * posf;

    ((float*)g_scale4)[col] = lam * crossf + posf;
    ((float*)g_val4)[col]   = delta * 0.5f * crossf;
    ((int*)g_cross4)[col]   = cross ? 1 : 0;
    out[col] = center;

    // block-local exclusive scan of crossing flags -> rank
    int flag = cross ? 1 : 0;
    int v = flag;
    #pragma unroll
    for (int o = 1; o < 32; o <<= 1) {
        int n = __shfl_up_sync(0xffffffffu, v, o);
        if (lane >= o) v += n;
    }
    if (lane == 31) s_wsum[wid] = v;
    __syncthreads();
    if (t < 8) {
        int wv = s_wsum[t];
        #pragma unroll
        for (int o = 1; o < 8; o <<= 1) {
            int n = __shfl_up_sync(0x000000ffu, wv, o);
            if (t >= o) wv += n;
        }
        s_wsum[t] = wv;
        if (t == 7) g_bcount[b] = wv;
    }
    __syncthreads();

    int rank = (v - flag) + ((wid > 0) ? s_wsum[wid - 1] : 0);
    ((int*)g_rank4)[col] = rank;
}

// K3: y<256 -> gens 8-row tiles (rows 1..2047); y==256 -> scatter into zeroed tail.
__global__ __launch_bounds__(256) void k3_gens_scatter(const float* __restrict__ x,
                                                       float* __restrict__ out) {
    int cy = blockIdx.y;
    if (cy < 256) {
        int col4 = blockIdx.x * blockDim.x + threadIdx.x;   // 0..1023
        const float4* x4 = (const float4*)x;
        float4* o4 = (float4*)out;
        float4 sc = g_scale4[col4];
        int r0 = 1 + cy * 8;
        #pragma unroll
        for (int r = 0; r < 8; r++) {
            int row = r0 + r;
            if (row < N_TERMS) {
                float4 v = x4[(size_t)row * COL4 + col4];
                v.x *= sc.x; v.y *= sc.y; v.z *= sc.z; v.w *= sc.w;
                o4[(size_t)row * COL4 + col4] = v;
            }
        }
    } else {
        // 4 x-blocks * 256 threads = 1024 threads, 4 consecutive columns each
        int i = blockIdx.x * blockDim.x + threadIdx.x;      // 0..1023
        int4   cf  = g_cross4[i];
        int4   rk  = g_rank4[i];
        float4 val = g_val4[i];
        int blk = i >> 6;                                   // (4*i)/256
        int base = 0;
        #pragma unroll
        for (int k = 0; k < K2_BLOCKS; k++)
            base += (k < blk) ? g_bcount[k] : 0;

        int col = i * 4;
        if (cf.x) out[(size_t)(N_TERMS + base + rk.x) * N_COLS + col + 0] = val.x;
        if (cf.y) out[(size_t)(N_TERMS + base + rk.y) * N_COLS + col + 1] = val.y;
        if (cf.z) out[(size_t)(N_TERMS + base + rk.z) * N_COLS + col + 2] = val.z;
        if (cf.w) out[(size_t)(N_TERMS + base + rk.w) * N_COLS + col + 3] = val.w;
    }
}

extern "C" void kernel_launch(void* const* d_in, const int* in_sizes, int n_in,
                              void* d_out, int out_size) {
    const float* x = (const float*)d_in[0];
    float* out     = (float*)d_out;

    k1_reduce_zero<<<K1_BLOCKS, 256>>>(x, out);
    k2_stats<<<K2_BLOCKS, 256>>>(x, out);
    dim3 g3(COL4 / 256, 257);                            // (4, 257)
    k3_gens_scatter<<<g3, 256>>>(x, out);
}

// round 10
// speedup vs baseline: 1.4665x; 1.3469x over previous
#include <cuda_runtime.h>
#include <cuda_bf16.h>

#define N_COLS   4096
#define N_TERMS  2048
#define COL4     1024              // float4 columns
#define ROW_BLOCKS 128
#define ROWS_PER   16
#define K2_BLOCKS  16              // 16 blocks x 256 threads = 4096 columns

// ---- scratch (device globals; no allocation allowed) ----
__device__ float  g_partial[ROW_BLOCKS * N_COLS];   // 2 MB partial |x| column sums
__device__ float4 g_scale4[COL4];                   // per-column generator scale
__device__ float4 g_val4[COL4];                     // per-column delta*0.5*crossf
__device__ int4   g_cross4[COL4];                   // per-column crossing flag
__device__ int4   g_rank4[COL4];                    // per-column local rank in 256-col slice
__device__ int    g_bcount[K2_BLOCKS];              // crossings per 256-col slice

// K1 (segregated, proven at LTS cap): y<128 -> |x| partial column sums;
// y>=128 -> zero tail rows 2048..6143 with evict-streaming stores.
__global__ __launch_bounds__(256) void k1_reduce_zero(const float* __restrict__ x,
                                                      float* __restrict__ out) {
    int col4 = blockIdx.x * blockDim.x + threadIdx.x;   // 0..1023
    int cy   = blockIdx.y;                              // 0..383

    if (cy < ROW_BLOCKS) {
        const float4* x4 = (const float4*)x;
        int r0 = 1 + cy * ROWS_PER;
        float4 acc = make_float4(0.f, 0.f, 0.f, 0.f);
        #pragma unroll
        for (int r = 0; r < ROWS_PER; r++) {
            int row = r0 + r;
            if (row < N_TERMS) {
                float4 v = x4[(size_t)row * COL4 + col4];
                acc.x += fabsf(v.x);
                acc.y += fabsf(v.y);
                acc.z += fabsf(v.z);
                acc.w += fabsf(v.w);
            }
        }
        ((float4*)&g_partial[cy * N_COLS])[col4] = acc;
    } else {
        float4* o4 = (float4*)out;
        int r0 = N_TERMS + (cy - ROW_BLOCKS) * ROWS_PER;
        const float4 z = make_float4(0.f, 0.f, 0.f, 0.f);
        #pragma unroll
        for (int r = 0; r < ROWS_PER; r++)
            __stcs(&o4[(size_t)(r0 + r) * COL4 + col4], z);
    }
}

// K2: per-column stats + center row + block-local scan of crossing flags.
__global__ __launch_bounds__(256) void k2_stats(const float* __restrict__ x,
                                                float* __restrict__ out) {
    __shared__ int s_wsum[8];
    int t   = threadIdx.x;                  // 0..255
    int b   = blockIdx.x;                   // 0..15
    int col = b * 256 + t;
    int lane = t & 31, wid = t >> 5;        // 8 warps

    float s = 0.f;
    #pragma unroll 16
    for (int rb = 0; rb < ROW_BLOCKS; rb++)
        s += g_partial[rb * N_COLS + col];

    float c     = x[col];                   // x[0] center row
    float upper = c + s;
    float lower = c - s;
    bool  cross = (lower * upper) < 0.f;
    bool  pos   = lower >= 0.f;
    float crossf = cross ? 1.f : 0.f;
    float posf   = pos   ? 1.f : 0.f;

    float denom = upper - lower;
    float ratio = (denom != 0.f) ? (upper / denom) : 0.5f;
    float lam   = posf + crossf * ratio;

    float delta  = fmaxf(-lam * lower, (1.f - lam) * upper);
    float center = (delta * 0.5f + lam * c) * crossf + c * posf;

    ((float*)g_scale4)[col] = lam * crossf + posf;
    ((float*)g_val4)[col]   = delta * 0.5f * crossf;
    ((int*)g_cross4)[col]   = cross ? 1 : 0;
    out[col] = center;

    // block-local exclusive scan of crossing flags -> rank
    int flag = cross ? 1 : 0;
    int v = flag;
    #pragma unroll
    for (int o = 1; o < 32; o <<= 1) {
        int n = __shfl_up_sync(0xffffffffu, v, o);
        if (lane >= o) v += n;
    }
    if (lane == 31) s_wsum[wid] = v;
    __syncthreads();
    if (t < 8) {
        int wv = s_wsum[t];
        #pragma unroll
        for (int o = 1; o < 8; o <<= 1) {
            int n = __shfl_up_sync(0x000000ffu, wv, o);
            if (t >= o) wv += n;
        }
        s_wsum[t] = wv;
        if (t == 7) g_bcount[b] = wv;
    }
    __syncthreads();

    int rank = (v - flag) + ((wid > 0) ? s_wsum[wid - 1] : 0);
    ((int*)g_rank4)[col] = rank;
}

// K3: y<256 -> gens 8-row tiles (rows 1..2047); y==256 -> scatter into zeroed tail.
__global__ __launch_bounds__(256) void k3_gens_scatter(const float* __restrict__ x,
                                                       float* __restrict__ out) {
    int cy = blockIdx.y;
    if (cy < 256) {
        int col4 = blockIdx.x * blockDim.x + threadIdx.x;   // 0..1023
        const float4* x4 = (const float4*)x;
        float4* o4 = (float4*)out;
        float4 sc = g_scale4[col4];
        int r0 = 1 + cy * 8;
        #pragma unroll
        for (int r = 0; r < 8; r++) {
            int row = r0 + r;
            if (row < N_TERMS) {
                float4 v = x4[(size_t)row * COL4 + col4];
                v.x *= sc.x; v.y *= sc.y; v.z *= sc.z; v.w *= sc.w;
                __stcs(&o4[(size_t)row * COL4 + col4], v);
            }
        }
    } else {
        // 4 x-blocks * 256 threads = 1024 threads, 4 consecutive columns each
        int i = blockIdx.x * blockDim.x + threadIdx.x;      // 0..1023
        int4   cf  = g_cross4[i];
        int4   rk  = g_rank4[i];
        float4 val = g_val4[i];
        int blk = i >> 6;                                   // (4*i)/256
        int base = 0;
        #pragma unroll
        for (int k = 0; k < K2_BLOCKS; k++)
            base += (k < blk) ? g_bcount[k] : 0;

        int col = i * 4;
        if (cf.x) out[(size_t)(N_TERMS + base + rk.x) * N_COLS + col + 0] = val.x;
        if (cf.y) out[(size_t)(N_TERMS + base + rk.y) * N_COLS + col + 1] = val.y;
        if (cf.z) out[(size_t)(N_TERMS + base + rk.z) * N_COLS + col + 2] = val.z;
        if (cf.w) out[(size_t)(N_TERMS + base + rk.w) * N_COLS + col + 3] = val.w;
    }
}

extern "C" void kernel_launch(void* const* d_in, const int* in_sizes, int n_in,
                              void* d_out, int out_size) {
    const float* x = (const float*)d_in[0];
    float* out     = (float*)d_out;

    dim3 g1(COL4 / 256, ROW_BLOCKS + N_COLS / ROWS_PER); // (4, 384)
    k1_reduce_zero<<<g1, 256>>>(x, out);
    k2_stats<<<K2_BLOCKS, 256>>>(x, out);
    dim3 g3(COL4 / 256, 257);                            // (4, 257)
    k3_gens_scatter<<<g3, 256>>>(x, out);
}